// round 1
// baseline (speedup 1.0000x reference)
#include <cuda_runtime.h>
#include <cuda_bf16.h>
#include <cstdint>

#define NB 8192
#define ND 512
#define NLAB 128
#define MARGIN 0.3f
#define INF_BITS 0x7f800000u

// ---------------- device scratch (no allocation allowed) ----------------
__device__ __nv_bfloat16 g_fn[NB * ND];     // normalized features, bf16 (8 MB)
__device__ float         g_sq[NB];          // sum of squares of bf16 row
__device__ int           g_lab[NB];         // labels as int32
__device__ float         g_mp[NB];          // mean positive distance
__device__ float         g_mp2[NB];         // mean_pos^2
__device__ int           g_cnt[NB];         // positive count (incl self)
__device__ unsigned int  g_mind2[NB];       // running min d2 (float bits)

// ---------------- helpers ----------------
__device__ __forceinline__ float warp_sum(float v) {
    #pragma unroll
    for (int o = 16; o > 0; o >>= 1) v += __shfl_xor_sync(0xffffffffu, v, o);
    return v;
}

__device__ __forceinline__ void mma16816(float* c, const unsigned* a, const unsigned* b) {
    asm volatile(
        "mma.sync.aligned.m16n8k16.row.col.f32.bf16.bf16.f32 "
        "{%0,%1,%2,%3},{%4,%5,%6,%7},{%8,%9},{%0,%1,%2,%3};\n"
        : "+f"(c[0]), "+f"(c[1]), "+f"(c[2]), "+f"(c[3])
        : "r"(a[0]), "r"(a[1]), "r"(a[2]), "r"(a[3]), "r"(b[0]), "r"(b[1]));
}

// ---------------- K1: normalize rows, quantize to bf16, init accumulators ----
__global__ void k1_normalize(const float* __restrict__ x,
                             const long long* __restrict__ lab64) {
    int r = blockIdx.x;
    int tid = threadIdx.x;            // 128 threads
    __shared__ float red[4];

    float v[4];
    #pragma unroll
    for (int i = 0; i < 4; i++) v[i] = x[(size_t)r * ND + tid + i * 128];

    float s = v[0]*v[0] + v[1]*v[1] + v[2]*v[2] + v[3]*v[3];
    s = warp_sum(s);
    if ((tid & 31) == 0) red[tid >> 5] = s;
    __syncthreads();
    float tot = red[0] + red[1] + red[2] + red[3];
    float norm = sqrtf(tot);
    float inv = 1.0f / fmaxf(norm, 1e-12f);

    float s2 = 0.f;
    #pragma unroll
    for (int i = 0; i < 4; i++) {
        __nv_bfloat16 bf = __float2bfloat16(v[i] * inv);
        g_fn[(size_t)r * ND + tid + i * 128] = bf;
        float fb = __bfloat162float(bf);
        s2 += fb * fb;
    }
    __syncthreads();                  // protect red[] reuse
    s2 = warp_sum(s2);
    if ((tid & 31) == 0) red[tid >> 5] = s2;
    __syncthreads();
    if (tid == 0) {
        g_sq[r] = red[0] + red[1] + red[2] + red[3];
        g_lab[r] = (int)lab64[r];
        g_mind2[r] = INF_BITS;        // reset every launch (graph replay safe)
    }
}

// ---------------- K2: per-label mean positive distance ----------------
#define MAXG 512
#define CHUNK 40
__global__ void k2_meanpos() {
    __shared__ int   s_idx[MAXG];
    __shared__ float s_sum[MAXG];
    __shared__ int   s_scan[256];
    __shared__ __align__(16) __nv_bfloat16 s_feat[CHUNK * ND]; // 40 KB

    int L = blockIdx.x;
    int tid = threadIdx.x;            // 256 threads
    int w = tid >> 5, lane = tid & 31;

    // deterministic ordered compaction of members of label L
    int c = 0;
    for (int j = tid; j < NB; j += 256) c += (g_lab[j] == L);
    s_scan[tid] = c;
    __syncthreads();
    #pragma unroll
    for (int off = 1; off < 256; off <<= 1) {
        int v = 0;
        if (tid >= off) v = s_scan[tid - off];
        __syncthreads();
        s_scan[tid] += v;
        __syncthreads();
    }
    int total = s_scan[255];
    int cnt = total < MAXG ? total : MAXG;
    int pos = s_scan[tid] - c;
    for (int j = tid; j < NB; j += 256) {
        if (g_lab[j] == L) { if (pos < MAXG) s_idx[pos] = j; pos++; }
    }
    for (int t = tid; t < cnt; t += 256) s_sum[t] = 0.f;
    __syncthreads();

    for (int cs = 0; cs < cnt; cs += CHUNK) {
        int nb = cnt - cs; if (nb > CHUNK) nb = CHUNK;
        __syncthreads();
        // stage chunk rows to smem (uint4 = 8 bf16)
        for (int v = tid; v < nb * 64; v += 256) {
            int b = v >> 6, c8 = v & 63;
            *(uint4*)&s_feat[b * ND + c8 * 8] =
                *(const uint4*)(g_fn + (size_t)s_idx[cs + b] * ND + c8 * 8);
        }
        __syncthreads();

        for (int ai = w; ai < cnt; ai += 8) {
            int ia = s_idx[ai];
            // anchor row: 16 bf16 per lane
            float af[16];
            {
                const uint4* pa = (const uint4*)(g_fn + (size_t)ia * ND + lane * 16);
                uint4 u0 = pa[0], u1 = pa[1];
                const __nv_bfloat162* h0 = (const __nv_bfloat162*)&u0;
                const __nv_bfloat162* h1 = (const __nv_bfloat162*)&u1;
                #pragma unroll
                for (int q = 0; q < 4; q++) {
                    float2 f0 = __bfloat1622float2(h0[q]);
                    float2 f1 = __bfloat1622float2(h1[q]);
                    af[2*q] = f0.x; af[2*q+1] = f0.y;
                    af[8+2*q] = f1.x; af[8+2*q+1] = f1.y;
                }
            }
            float sq_a = g_sq[ia];
            float lsum = 0.f;
            for (int b = 0; b < nb; b++) {
                const __nv_bfloat162* pb =
                    (const __nv_bfloat162*)&s_feat[b * ND + lane * 16];
                float d = 0.f;
                #pragma unroll
                for (int q = 0; q < 8; q++) {
                    float2 fv = __bfloat1622float2(pb[q]);
                    d += af[2*q] * fv.x + af[2*q+1] * fv.y;
                }
                d = warp_sum(d);
                int ib = s_idx[cs + b];
                if (lane == 0 && ib != ia) {
                    float d2 = sq_a + g_sq[ib] - 2.f * d;
                    d2 = fmaxf(d2, 0.f);
                    if (d2 > 0.f) lsum += sqrtf(d2);
                }
            }
            if (lane == 0) s_sum[ai] += lsum;   // chunk order sequential: deterministic
        }
    }
    __syncthreads();
    for (int t = tid; t < cnt; t += 256) {
        int i = s_idx[t];
        float mp = s_sum[t] / (float)cnt;
        g_mp[i] = mp;
        g_mp2[i] = mp * mp;
        g_cnt[i] = cnt;
    }
}

// ---------------- K3: full Gram pass + semi-hard min epilogue ----------------
// BM=BN=128, BK=64, 256 threads (8 warps, 4 row x 2 col), warp tile 32x64.
__global__ __launch_bounds__(256, 2) void k3_gram_min() {
    __shared__ __align__(16) __nv_bfloat16 As[128 * 72];
    __shared__ __align__(16) __nv_bfloat16 Bs[128 * 72];
    __shared__ int   s_labj[128];
    __shared__ float s_sqj[128];

    int tid = threadIdx.x;
    int w = tid >> 5, l = tid & 31;
    int wr = w >> 1, wc = w & 1;
    int g = l >> 2, tig = l & 3;

    int rowBase = blockIdx.x * 128;
    int colBase0 = blockIdx.y * 2048;

    int myRow[4]; int labi[4];
    float sqi[4], mp2i[4], mind2[4];
    #pragma unroll
    for (int mt = 0; mt < 2; mt++)
        #pragma unroll
        for (int h = 0; h < 2; h++) {
            int ri = mt * 2 + h;
            int r = rowBase + wr * 32 + mt * 16 + h * 8 + g;
            myRow[ri] = r;
            sqi[ri] = g_sq[r];
            mp2i[ri] = g_mp2[r];
            labi[ri] = g_lab[r];
            mind2[ri] = __uint_as_float(INF_BITS);
        }

    for (int jt = 0; jt < 16; jt++) {
        int colsBase = colBase0 + jt * 128;
        __syncthreads();                       // prev epilogue done with s_labj
        if (tid < 128) {
            s_labj[tid] = g_lab[colsBase + tid];
            s_sqj[tid] = g_sq[colsBase + tid];
        }
        float acc[2][8][4];
        #pragma unroll
        for (int mt = 0; mt < 2; mt++)
            #pragma unroll
            for (int nt = 0; nt < 8; nt++)
                #pragma unroll
                for (int e = 0; e < 4; e++) acc[mt][nt][e] = 0.f;

        for (int ks = 0; ks < 8; ks++) {
            int k0 = ks * 64;
            __syncthreads();                   // prev mma done with smem
            #pragma unroll
            for (int v = 0; v < 4; v++) {
                int idx = tid + v * 256;
                int r = idx >> 3, c8 = idx & 7;
                *(uint4*)&As[r * 72 + c8 * 8] =
                    *(const uint4*)(g_fn + (size_t)(rowBase + r) * ND + k0 + c8 * 8);
                *(uint4*)&Bs[r * 72 + c8 * 8] =
                    *(const uint4*)(g_fn + (size_t)(colsBase + r) * ND + k0 + c8 * 8);
            }
            __syncthreads();
            #pragma unroll
            for (int kk = 0; kk < 4; kk++) {
                int kb = kk * 16 + 2 * tig;
                unsigned a[2][4];
                #pragma unroll
                for (int mt = 0; mt < 2; mt++) {
                    int r0 = wr * 32 + mt * 16 + g;
                    a[mt][0] = *(const unsigned*)&As[r0 * 72 + kb];
                    a[mt][1] = *(const unsigned*)&As[(r0 + 8) * 72 + kb];
                    a[mt][2] = *(const unsigned*)&As[r0 * 72 + kb + 8];
                    a[mt][3] = *(const unsigned*)&As[(r0 + 8) * 72 + kb + 8];
                }
                #pragma unroll
                for (int nt = 0; nt < 8; nt++) {
                    int n0 = wc * 64 + nt * 8 + g;
                    unsigned b[2];
                    b[0] = *(const unsigned*)&Bs[n0 * 72 + kb];
                    b[1] = *(const unsigned*)&Bs[n0 * 72 + kb + 8];
                    mma16816(acc[0][nt], a[0], b);
                    mma16816(acc[1][nt], a[1], b);
                }
            }
        }
        // epilogue: fuse d2 + semi-hard min
        #pragma unroll
        for (int mt = 0; mt < 2; mt++)
            #pragma unroll
            for (int nt = 0; nt < 8; nt++)
                #pragma unroll
                for (int e = 0; e < 4; e++) {
                    int h = e >> 1, ri = mt * 2 + h;
                    int ct = wc * 64 + nt * 8 + 2 * tig + (e & 1);
                    float dot = acc[mt][nt][e];
                    float d2 = sqi[ri] + s_sqj[ct] - 2.f * dot;
                    d2 = fmaxf(d2, 0.f);
                    if (s_labj[ct] != labi[ri] && d2 > mp2i[ri])
                        mind2[ri] = fminf(mind2[ri], d2);
                }
    }
    // combine 4 lanes sharing a row, then global atomicMin (float bits, d2>=0)
    #pragma unroll
    for (int ri = 0; ri < 4; ri++) {
        float v = mind2[ri];
        v = fminf(v, __shfl_xor_sync(0xffffffffu, v, 1));
        v = fminf(v, __shfl_xor_sync(0xffffffffu, v, 2));
        if (tig == 0) atomicMin(&g_mind2[myRow[ri]], __float_as_uint(v));
    }
}

// ---------------- K4: final reduction ----------------
__global__ void k4_finalize(float* __restrict__ out) {
    __shared__ float ssum[256];
    __shared__ int   scnt[256];
    int tid = threadIdx.x;
    float s = 0.f; int c = 0;
    for (int i = tid; i < NB; i += 256) {
        int pc = g_cnt[i];
        unsigned u = g_mind2[i];
        if (pc > 1 && pc < NB && u < INF_BITS) {
            float md = sqrtf(__uint_as_float(u));
            float per = g_mp[i] - md + MARGIN;
            if (per > 0.f) s += per;
            c++;
        }
    }
    ssum[tid] = s; scnt[tid] = c;
    __syncthreads();
    #pragma unroll
    for (int off = 128; off > 0; off >>= 1) {
        if (tid < off) { ssum[tid] += ssum[tid + off]; scnt[tid] += scnt[tid + off]; }
        __syncthreads();
    }
    if (tid == 0) out[0] = (scnt[0] > 0) ? ssum[0] / (float)scnt[0] : 0.f;
}

// ---------------- launch ----------------
extern "C" void kernel_launch(void* const* d_in, const int* in_sizes, int n_in,
                              void* d_out, int out_size) {
    const float* features = (const float*)d_in[0];
    const long long* labels = (const long long*)d_in[1];
    float* out = (float*)d_out;

    k1_normalize<<<NB, 128>>>(features, labels);
    k2_meanpos<<<NLAB, 256>>>();
    k3_gram_min<<<dim3(64, 4), 256>>>();
    k4_finalize<<<1, 256>>>(out);
}

// round 2
// speedup vs baseline: 1.0045x; 1.0045x over previous
#include <cuda_runtime.h>
#include <cuda_bf16.h>
#include <cstdint>

#define NB 8192
#define ND 512
#define NLAB 128
#define MARGIN 0.3f
#define INF_BITS 0x7f800000u

// ---------------- device scratch (no allocation allowed) ----------------
__device__ __nv_bfloat16 g_fn[NB * ND];     // normalized features, bf16 (8 MB)
__device__ float         g_sq[NB];          // sum of squares of bf16 row
__device__ int           g_lab[NB];         // labels as int32
__device__ float         g_mp[NB];          // mean positive distance
__device__ float         g_mp2[NB];         // mean_pos^2
__device__ int           g_cnt[NB];         // positive count (incl self)
__device__ unsigned int  g_mind2[NB];       // running min d2 (float bits)

// ---------------- helpers ----------------
__device__ __forceinline__ float warp_sum(float v) {
    #pragma unroll
    for (int o = 16; o > 0; o >>= 1) v += __shfl_xor_sync(0xffffffffu, v, o);
    return v;
}

__device__ __forceinline__ void mma16816(float* c, const unsigned* a, const unsigned* b) {
    asm volatile(
        "mma.sync.aligned.m16n8k16.row.col.f32.bf16.bf16.f32 "
        "{%0,%1,%2,%3},{%4,%5,%6,%7},{%8,%9},{%0,%1,%2,%3};\n"
        : "+f"(c[0]), "+f"(c[1]), "+f"(c[2]), "+f"(c[3])
        : "r"(a[0]), "r"(a[1]), "r"(a[2]), "r"(a[3]), "r"(b[0]), "r"(b[1]));
}

__device__ __forceinline__ void cp16(void* dst, const void* src) {
    unsigned d = (unsigned)__cvta_generic_to_shared(dst);
    asm volatile("cp.async.cg.shared.global [%0], [%1], 16;\n" :: "r"(d), "l"(src));
}
__device__ __forceinline__ void cp_commit() {
    asm volatile("cp.async.commit_group;\n");
}
template <int N>
__device__ __forceinline__ void cp_wait() {
    asm volatile("cp.async.wait_group %0;\n" :: "n"(N));
}

// ---------------- K1: normalize rows, quantize to bf16, init accumulators ----
__global__ void k1_normalize(const float* __restrict__ x,
                             const long long* __restrict__ lab64) {
    int r = blockIdx.x;
    int tid = threadIdx.x;            // 128 threads
    __shared__ float red[4];

    float v[4];
    #pragma unroll
    for (int i = 0; i < 4; i++) v[i] = x[(size_t)r * ND + tid + i * 128];

    float s = v[0]*v[0] + v[1]*v[1] + v[2]*v[2] + v[3]*v[3];
    s = warp_sum(s);
    if ((tid & 31) == 0) red[tid >> 5] = s;
    __syncthreads();
    float tot = red[0] + red[1] + red[2] + red[3];
    float norm = sqrtf(tot);
    float inv = 1.0f / fmaxf(norm, 1e-12f);

    float s2 = 0.f;
    #pragma unroll
    for (int i = 0; i < 4; i++) {
        __nv_bfloat16 bf = __float2bfloat16(v[i] * inv);
        g_fn[(size_t)r * ND + tid + i * 128] = bf;
        float fb = __bfloat162float(bf);
        s2 += fb * fb;
    }
    __syncthreads();                  // protect red[] reuse
    s2 = warp_sum(s2);
    if ((tid & 31) == 0) red[tid >> 5] = s2;
    __syncthreads();
    if (tid == 0) {
        g_sq[r] = red[0] + red[1] + red[2] + red[3];
        g_lab[r] = (int)lab64[r];
        g_mind2[r] = INF_BITS;        // reset every launch (graph replay safe)
    }
}

// ---------------- K2: per-label mean positive distance ----------------
#define MAXG 512
#define CHUNK 40
__global__ void k2_meanpos() {
    __shared__ int   s_idx[MAXG];
    __shared__ float s_sum[MAXG];
    __shared__ int   s_scan[256];
    __shared__ __align__(16) __nv_bfloat16 s_feat[CHUNK * ND]; // 40 KB

    int L = blockIdx.x;
    int tid = threadIdx.x;            // 256 threads
    int w = tid >> 5, lane = tid & 31;

    // deterministic ordered compaction of members of label L
    int c = 0;
    for (int j = tid; j < NB; j += 256) c += (g_lab[j] == L);
    s_scan[tid] = c;
    __syncthreads();
    #pragma unroll
    for (int off = 1; off < 256; off <<= 1) {
        int v = 0;
        if (tid >= off) v = s_scan[tid - off];
        __syncthreads();
        s_scan[tid] += v;
        __syncthreads();
    }
    int total = s_scan[255];
    int cnt = total < MAXG ? total : MAXG;
    int pos = s_scan[tid] - c;
    for (int j = tid; j < NB; j += 256) {
        if (g_lab[j] == L) { if (pos < MAXG) s_idx[pos] = j; pos++; }
    }
    for (int t = tid; t < cnt; t += 256) s_sum[t] = 0.f;
    __syncthreads();

    for (int cs = 0; cs < cnt; cs += CHUNK) {
        int nb = cnt - cs; if (nb > CHUNK) nb = CHUNK;
        __syncthreads();
        // stage chunk rows to smem (uint4 = 8 bf16)
        for (int v = tid; v < nb * 64; v += 256) {
            int b = v >> 6, c8 = v & 63;
            *(uint4*)&s_feat[b * ND + c8 * 8] =
                *(const uint4*)(g_fn + (size_t)s_idx[cs + b] * ND + c8 * 8);
        }
        __syncthreads();

        for (int ai = w; ai < cnt; ai += 8) {
            int ia = s_idx[ai];
            // anchor row: 16 bf16 per lane
            float af[16];
            {
                const uint4* pa = (const uint4*)(g_fn + (size_t)ia * ND + lane * 16);
                uint4 u0 = pa[0], u1 = pa[1];
                const __nv_bfloat162* h0 = (const __nv_bfloat162*)&u0;
                const __nv_bfloat162* h1 = (const __nv_bfloat162*)&u1;
                #pragma unroll
                for (int q = 0; q < 4; q++) {
                    float2 f0 = __bfloat1622float2(h0[q]);
                    float2 f1 = __bfloat1622float2(h1[q]);
                    af[2*q] = f0.x; af[2*q+1] = f0.y;
                    af[8+2*q] = f1.x; af[8+2*q+1] = f1.y;
                }
            }
            float sq_a = g_sq[ia];
            float lsum = 0.f;
            for (int b = 0; b < nb; b++) {
                const __nv_bfloat162* pb =
                    (const __nv_bfloat162*)&s_feat[b * ND + lane * 16];
                float d = 0.f;
                #pragma unroll
                for (int q = 0; q < 8; q++) {
                    float2 fv = __bfloat1622float2(pb[q]);
                    d += af[2*q] * fv.x + af[2*q+1] * fv.y;
                }
                d = warp_sum(d);
                int ib = s_idx[cs + b];
                if (lane == 0 && ib != ia) {
                    float d2 = sq_a + g_sq[ib] - 2.f * d;
                    d2 = fmaxf(d2, 0.f);
                    if (d2 > 0.f) lsum += sqrtf(d2);
                }
            }
            if (lane == 0) s_sum[ai] += lsum;   // chunk order sequential: deterministic
        }
    }
    __syncthreads();
    for (int t = tid; t < cnt; t += 256) {
        int i = s_idx[t];
        float mp = s_sum[t] / (float)cnt;
        g_mp[i] = mp;
        g_mp2[i] = mp * mp;
        g_cnt[i] = cnt;
    }
}

// ---------------- K3: full Gram pass + semi-hard min epilogue ----------------
// Block tile 128 rows x (32 x 128) cols, K=512.
// Full A tile resident in smem (128x520 bf16), B double-buffered via cp.async.
// 256 threads = 8 warps (4 row x 2 col), warp tile 32x64.
#define A_ST 520
#define B_ST 72
#define JT 32
#define A_BYTES (128 * A_ST * 2)              // 133120
#define B_BYTES (2 * 128 * B_ST * 2)          // 36864
#define LAB_OFF (A_BYTES + B_BYTES)           // 169984
#define SQ_OFF  (LAB_OFF + 2 * 128 * 4)       // 171008
#define SMEM_BYTES (SQ_OFF + 2 * 128 * 4)     // 172032

extern __shared__ char smem_raw[];

__global__ __launch_bounds__(256) void k3_gram_min() {
    __nv_bfloat16* As = (__nv_bfloat16*)smem_raw;
    __nv_bfloat16* Bs = (__nv_bfloat16*)(smem_raw + A_BYTES);
    int*   s_labj = (int*)(smem_raw + LAB_OFF);
    float* s_sqj  = (float*)(smem_raw + SQ_OFF);

    int tid = threadIdx.x;
    int w = tid >> 5, l = tid & 31;
    int wr = w >> 1, wc = w & 1;
    int g = l >> 2, tig = l & 3;

    int rowBase = blockIdx.x * 128;
    int colBase0 = blockIdx.y * (JT * 128);

    // per-row state for the 4 output rows this thread touches
    int myRow[4]; int labi[4];
    float sqi[4], mp2i[4], mind2[4];
    #pragma unroll
    for (int mt = 0; mt < 2; mt++)
        #pragma unroll
        for (int h = 0; h < 2; h++) {
            int ri = mt * 2 + h;
            int r = rowBase + wr * 32 + mt * 16 + h * 8 + g;
            myRow[ri] = r;
            sqi[ri] = g_sq[r];
            mp2i[ri] = g_mp2[r];
            labi[ri] = g_lab[r];
            mind2[ri] = __uint_as_float(INF_BITS);
        }

    // ---- load full A tile (128 x 512) via cp.async: 32 x 16B per thread ----
    #pragma unroll
    for (int v = 0; v < 32; v++) {
        int idx = tid + v * 256;
        int r = idx >> 6, c8 = idx & 63;
        cp16(As + r * A_ST + c8 * 8,
             g_fn + (size_t)(rowBase + r) * ND + c8 * 8);
    }
    // ---- B tile (jt=0, ks=0) into buf 0 ----
    #pragma unroll
    for (int v = 0; v < 4; v++) {
        int idx = tid + v * 256;
        int r = idx >> 3, c8 = idx & 7;
        cp16(Bs + r * B_ST + c8 * 8,
             g_fn + (size_t)(colBase0 + r) * ND + c8 * 8);
    }
    cp_commit();
    // labels for jt=0 into buf 0
    if (tid < 128) {
        s_labj[tid] = g_lab[colBase0 + tid];
        s_sqj[tid]  = g_sq[colBase0 + tid];
    }
    cp_wait<0>();
    __syncthreads();

    float acc[2][8][4];

    const int TOTAL = JT * 8;
    for (int it = 0; it < TOTAL; it++) {
        int jt = it >> 3, ks = it & 7;
        int nxt = it + 1;
        if (nxt < TOTAL) {
            int jn = nxt >> 3, kn = nxt & 7;
            int colsN = colBase0 + jn * 128;
            __nv_bfloat16* Bd = Bs + (nxt & 1) * 128 * B_ST;
            #pragma unroll
            for (int v = 0; v < 4; v++) {
                int idx = tid + v * 256;
                int r = idx >> 3, c8 = idx & 7;
                cp16(Bd + r * B_ST + c8 * 8,
                     g_fn + (size_t)(colsN + r) * ND + kn * 64 + c8 * 8);
            }
            cp_commit();
            if (kn == 0 && tid < 128) {    // new col tile: stage its labels
                s_labj[(jn & 1) * 128 + tid] = g_lab[colsN + tid];
                s_sqj [(jn & 1) * 128 + tid] = g_sq [colsN + tid];
            }
            cp_wait<1>();
        } else {
            cp_wait<0>();
        }
        __syncthreads();

        if (ks == 0) {
            #pragma unroll
            for (int mt = 0; mt < 2; mt++)
                #pragma unroll
                for (int nt = 0; nt < 8; nt++)
                    #pragma unroll
                    for (int e = 0; e < 4; e++) acc[mt][nt][e] = 0.f;
        }

        const __nv_bfloat16* Bb = Bs + (it & 1) * 128 * B_ST;
        #pragma unroll
        for (int kk = 0; kk < 4; kk++) {
            int kbB = kk * 16 + 2 * tig;            // within B tile (64 wide)
            int kbA = ks * 64 + kbB;                // within full-K A tile
            unsigned a[2][4];
            #pragma unroll
            for (int mt = 0; mt < 2; mt++) {
                int r0 = wr * 32 + mt * 16 + g;
                a[mt][0] = *(const unsigned*)&As[r0 * A_ST + kbA];
                a[mt][1] = *(const unsigned*)&As[(r0 + 8) * A_ST + kbA];
                a[mt][2] = *(const unsigned*)&As[r0 * A_ST + kbA + 8];
                a[mt][3] = *(const unsigned*)&As[(r0 + 8) * A_ST + kbA + 8];
            }
            #pragma unroll
            for (int nt = 0; nt < 8; nt++) {
                int n0 = wc * 64 + nt * 8 + g;
                unsigned b[2];
                b[0] = *(const unsigned*)&Bb[n0 * B_ST + kbB];
                b[1] = *(const unsigned*)&Bb[n0 * B_ST + kbB + 8];
                mma16816(acc[0][nt], a[0], b);
                mma16816(acc[1][nt], a[1], b);
            }
        }

        if (ks == 7) {
            // epilogue: fuse d2 + semi-hard min for this col tile
            int lb = (jt & 1) * 128;
            #pragma unroll
            for (int mt = 0; mt < 2; mt++)
                #pragma unroll
                for (int nt = 0; nt < 8; nt++)
                    #pragma unroll
                    for (int e = 0; e < 4; e++) {
                        int h = e >> 1, ri = mt * 2 + h;
                        int ct = wc * 64 + nt * 8 + 2 * tig + (e & 1);
                        float dot = acc[mt][nt][e];
                        float d2 = sqi[ri] + s_sqj[lb + ct] - 2.f * dot;
                        d2 = fmaxf(d2, 0.f);
                        if (s_labj[lb + ct] != labi[ri] && d2 > mp2i[ri])
                            mind2[ri] = fminf(mind2[ri], d2);
                    }
        }
        __syncthreads();
    }

    // combine 4 lanes sharing a row, then global atomicMin (float bits, d2>=0)
    #pragma unroll
    for (int ri = 0; ri < 4; ri++) {
        float v = mind2[ri];
        v = fminf(v, __shfl_xor_sync(0xffffffffu, v, 1));
        v = fminf(v, __shfl_xor_sync(0xffffffffu, v, 2));
        if (tig == 0) atomicMin(&g_mind2[myRow[ri]], __float_as_uint(v));
    }
}

// ---------------- K4: final reduction ----------------
__global__ void k4_finalize(float* __restrict__ out) {
    __shared__ float ssum[256];
    __shared__ int   scnt[256];
    int tid = threadIdx.x;
    float s = 0.f; int c = 0;
    for (int i = tid; i < NB; i += 256) {
        int pc = g_cnt[i];
        unsigned u = g_mind2[i];
        if (pc > 1 && pc < NB && u < INF_BITS) {
            float md = sqrtf(__uint_as_float(u));
            float per = g_mp[i] - md + MARGIN;
            if (per > 0.f) s += per;
            c++;
        }
    }
    ssum[tid] = s; scnt[tid] = c;
    __syncthreads();
    #pragma unroll
    for (int off = 128; off > 0; off >>= 1) {
        if (tid < off) { ssum[tid] += ssum[tid + off]; scnt[tid] += scnt[tid + off]; }
        __syncthreads();
    }
    if (tid == 0) out[0] = (scnt[0] > 0) ? ssum[0] / (float)scnt[0] : 0.f;
}

// ---------------- launch ----------------
extern "C" void kernel_launch(void* const* d_in, const int* in_sizes, int n_in,
                              void* d_out, int out_size) {
    const float* features = (const float*)d_in[0];
    const long long* labels = (const long long*)d_in[1];
    float* out = (float*)d_out;

    cudaFuncSetAttribute(k3_gram_min,
                         cudaFuncAttributeMaxDynamicSharedMemorySize, SMEM_BYTES);

    k1_normalize<<<NB, 128>>>(features, labels);
    k2_meanpos<<<NLAB, 256>>>();
    k3_gram_min<<<dim3(64, 2), 256, SMEM_BYTES>>>();
    k4_finalize<<<1, 256>>>(out);
}